// round 1
// baseline (speedup 1.0000x reference)
#include <cuda_runtime.h>

// Problem constants (fixed by the dataset)
static constexpr int NN  = 100000;   // nodes
static constexpr int NE  = 600000;   // edges
static constexpr int KD  = 128;      // in_dim == hidden (K of both GEMMs)
static constexpr int HID = 128;      // hidden width
static constexpr int FO  = 64;       // out width

// ---------------- scratch (device globals: no allocations allowed) ----------
__device__ int   g_is64;
__device__ int   g_src[NE];
__device__ int   g_dst[NE];
__device__ float g_deg[NN];
__device__ float g_dinv[NN];
__device__ float g_norm[NE];
__device__ float g_h1[(size_t)NN * HID];   // x @ W1
__device__ float g_a1[(size_t)NN * HID];   // aggregated layer-1 (pre bias/relu)
__device__ float g_h2[(size_t)NN * FO];    // relu(a1+b1) @ W2

// ---------------- edge-index width detection + normalization ----------------
__global__ void detect_kernel(const void* ei) {
    const int* p = (const int*)ei;
    bool z = (p[2 * threadIdx.x + 1] == 0);
    unsigned m = __ballot_sync(0xffffffffu, z);
    __shared__ int ok[2];
    if ((threadIdx.x & 31) == 0) ok[threadIdx.x >> 5] = (m == 0xffffffffu) ? 1 : 0;
    __syncthreads();
    if (threadIdx.x == 0) g_is64 = ok[0] & ok[1];
}

__global__ void convert_edges(const void* ei) {
    int e = blockIdx.x * blockDim.x + threadIdx.x;
    if (e >= NE) return;
    if (g_is64) {
        const long long* p = (const long long*)ei;
        g_src[e] = (int)p[e];
        g_dst[e] = (int)p[e + NE];
    } else {
        const int* p = (const int*)ei;
        g_src[e] = p[e];
        g_dst[e] = p[e + NE];
    }
}

// ---------------- degree / normalization ------------------------------------
__global__ void zero_deg_kernel() {
    int i = blockIdx.x * blockDim.x + threadIdx.x;
    if (i < NN) g_deg[i] = 0.0f;
}

__global__ void deg_accum_kernel() {
    int e = blockIdx.x * blockDim.x + threadIdx.x;
    if (e < NE) atomicAdd(&g_deg[g_dst[e]], 1.0f);
}

__global__ void dinv_kernel() {
    int i = blockIdx.x * blockDim.x + threadIdx.x;
    if (i < NN) {
        float d = g_deg[i] + 1.0f;  // + self-loop; always > 0
        g_dinv[i] = 1.0f / sqrtf(d);
    }
}

__global__ void norm_kernel() {
    int e = blockIdx.x * blockDim.x + threadIdx.x;
    if (e < NE) g_norm[e] = g_dinv[g_src[e]] * g_dinv[g_dst[e]];
}

// ---------------- fp32 tiled GEMM: C[M,NT] = op(A)[M,128] * W[128,NT] --------
// op(A) = relu(A + abias) when RELU, else A.  BM=64, BN=64, BK=16, 256 thr.
template <int NT, bool RELU>
__global__ void gemm_kernel(const float* __restrict__ A,
                            const float* __restrict__ abias,
                            const float* __restrict__ W,
                            float* __restrict__ C, int M) {
    __shared__ float As[16][65];  // [k][row], padded
    __shared__ float Ws[16][64];  // [k][col]

    const int tid = threadIdx.x;
    const int tx = tid & 15;      // output col group
    const int ty = tid >> 4;      // output row group
    const int rowBase = blockIdx.x * 64;
    const int colBase = blockIdx.y * 64;

    const int arow = tid >> 2;         // 0..63
    const int akq  = (tid & 3) * 4;    // 0,4,8,12
    const int wk   = tid >> 4;         // 0..15
    const int wc   = (tid & 15) * 4;   // 0..60

    float acc[4][4];
    #pragma unroll
    for (int i = 0; i < 4; i++)
        #pragma unroll
        for (int j = 0; j < 4; j++) acc[i][j] = 0.0f;

    for (int k0 = 0; k0 < KD; k0 += 16) {
        int gr = rowBase + arow;
        float4 av = make_float4(0.f, 0.f, 0.f, 0.f);
        if (gr < M) av = *(const float4*)(A + (size_t)gr * KD + k0 + akq);
        if (RELU) {
            float4 bb = *(const float4*)(abias + k0 + akq);
            av.x = fmaxf(av.x + bb.x, 0.f);
            av.y = fmaxf(av.y + bb.y, 0.f);
            av.z = fmaxf(av.z + bb.z, 0.f);
            av.w = fmaxf(av.w + bb.w, 0.f);
        }
        As[akq + 0][arow] = av.x;
        As[akq + 1][arow] = av.y;
        As[akq + 2][arow] = av.z;
        As[akq + 3][arow] = av.w;

        *(float4*)&Ws[wk][wc] =
            *(const float4*)(W + (size_t)(k0 + wk) * NT + colBase + wc);
        __syncthreads();

        #pragma unroll
        for (int kk = 0; kk < 16; kk++) {
            float4 b = *(const float4*)&Ws[kk][tx * 4];
            float a[4];
            #pragma unroll
            for (int i = 0; i < 4; i++) a[i] = As[kk][ty * 4 + i];
            #pragma unroll
            for (int i = 0; i < 4; i++) {
                acc[i][0] = fmaf(a[i], b.x, acc[i][0]);
                acc[i][1] = fmaf(a[i], b.y, acc[i][1]);
                acc[i][2] = fmaf(a[i], b.z, acc[i][2]);
                acc[i][3] = fmaf(a[i], b.w, acc[i][3]);
            }
        }
        __syncthreads();
    }

    #pragma unroll
    for (int i = 0; i < 4; i++) {
        int gr = rowBase + ty * 4 + i;
        if (gr < M) {
            *(float4*)(C + (size_t)gr * NT + colBase + tx * 4) =
                make_float4(acc[i][0], acc[i][1], acc[i][2], acc[i][3]);
        }
    }
}

// ---------------- aggregation ------------------------------------------------
// a1[n,:] = h1[n,:] * dinv[n]^2     (self-loop term, also initializes buffer)
__global__ void self_init128(const float* __restrict__ h, float* __restrict__ out) {
    int idx = blockIdx.x * blockDim.x + threadIdx.x;  // over NN*32 float4s
    if (idx >= NN * 32) return;
    int node = idx >> 5;
    float d = g_dinv[node];
    float w = d * d;
    float4 v = ((const float4*)h)[idx];
    v.x *= w; v.y *= w; v.z *= w; v.w *= w;
    ((float4*)out)[idx] = v;
}

// out[n,:] = h2[n,:] * dinv[n]^2 + b2
__global__ void self_init64(const float* __restrict__ h,
                            const float* __restrict__ bias,
                            float* __restrict__ out) {
    int idx = blockIdx.x * blockDim.x + threadIdx.x;  // over NN*16 float4s
    if (idx >= NN * 16) return;
    int node = idx >> 4;
    int q = idx & 15;
    float d = g_dinv[node];
    float w = d * d;
    float4 v = ((const float4*)h)[idx];
    float4 bb = ((const float4*)bias)[q];
    v.x = v.x * w + bb.x;
    v.y = v.y * w + bb.y;
    v.z = v.z * w + bb.z;
    v.w = v.w * w + bb.w;
    ((float4*)out)[idx] = v;
}

// warp per edge, 128 features: out[dst,:] += h[src,:] * norm
__global__ void agg_edges128(const float* __restrict__ h, float* __restrict__ out) {
    int t = blockIdx.x * blockDim.x + threadIdx.x;
    int e = t >> 5;
    int lane = t & 31;
    if (e >= NE) return;
    int s = g_src[e];
    int d = g_dst[e];
    float nm = g_norm[e];
    float4 v = ((const float4*)(h + (size_t)s * 128))[lane];
    float* o = out + (size_t)d * 128 + lane * 4;
    atomicAdd(o + 0, v.x * nm);
    atomicAdd(o + 1, v.y * nm);
    atomicAdd(o + 2, v.z * nm);
    atomicAdd(o + 3, v.w * nm);
}

// warp per edge, 64 features
__global__ void agg_edges64(const float* __restrict__ h, float* __restrict__ out) {
    int t = blockIdx.x * blockDim.x + threadIdx.x;
    int e = t >> 5;
    int lane = t & 31;
    if (e >= NE) return;
    int s = g_src[e];
    int d = g_dst[e];
    float nm = g_norm[e];
    float2 v = ((const float2*)(h + (size_t)s * 64))[lane];
    float* o = out + (size_t)d * 64 + lane * 2;
    atomicAdd(o + 0, v.x * nm);
    atomicAdd(o + 1, v.y * nm);
}

// ---------------- launcher ---------------------------------------------------
extern "C" void kernel_launch(void* const* d_in, const int* in_sizes, int n_in,
                              void* d_out, int out_size) {
    const float* x  = (const float*)d_in[0];
    const void*  ei = d_in[1];
    const float* W1 = (const float*)d_in[2];
    const float* b1 = (const float*)d_in[3];
    const float* W2 = (const float*)d_in[4];
    const float* b2 = (const float*)d_in[5];
    float* out = (float*)d_out;

    float* h1 = nullptr; float* a1 = nullptr; float* h2 = nullptr;
    cudaGetSymbolAddress((void**)&h1, g_h1);
    cudaGetSymbolAddress((void**)&a1, g_a1);
    cudaGetSymbolAddress((void**)&h2, g_h2);

    const int T = 256;
    // 1. edge preprocessing
    detect_kernel<<<1, 64>>>(ei);
    convert_edges<<<(NE + T - 1) / T, T>>>(ei);
    zero_deg_kernel<<<(NN + T - 1) / T, T>>>();
    deg_accum_kernel<<<(NE + T - 1) / T, T>>>();
    dinv_kernel<<<(NN + T - 1) / T, T>>>();
    norm_kernel<<<(NE + T - 1) / T, T>>>();

    // 2. layer 1: h1 = x @ W1, aggregate into a1
    {
        dim3 grid((NN + 63) / 64, HID / 64);
        gemm_kernel<HID, false><<<grid, 256>>>(x, nullptr, W1, h1, NN);
    }
    self_init128<<<(NN * 32 + T - 1) / T, T>>>(h1, a1);
    agg_edges128<<<(NE * 32 + T - 1) / T, T>>>(h1, a1);

    // 3. layer 2: h2 = relu(a1 + b1) @ W2, aggregate into out (+b2)
    {
        dim3 grid((NN + 63) / 64, FO / 64);
        gemm_kernel<FO, true><<<grid, 256>>>(a1, b1, W2, h2, NN);
    }
    self_init64<<<(NN * 16 + T - 1) / T, T>>>(h2, b2, out);
    agg_edges64<<<(NE * 32 + T - 1) / T, T>>>(h2, out);
}